// round 1
// baseline (speedup 1.0000x reference)
#include <cuda_runtime.h>
#include <math.h>
#include <float.h>

#define N      8192
#define C0     64
#define E      128
#define EXT    132          // 128 embedding + 3 xyz + 1 bias/norm term
#define KSEL   16
#define NSLICES 16
#define SLICE  (N / NSLICES)   // 512
#define TJ     8
#define DROWS  128

// ---------------- scratch (__device__ globals; no allocation allowed) ----------------
// combos: 0 = t11(feat1) [dir0 side1], 1 = t22(feat2) [dir0 side2],
//         2 = t11(feat2) [dir1 side1], 3 = t22(feat1) [dir1 side2]
__device__ float g_f[4][N][C0];        // projected features, row-major [n][c]
__device__ float g_gt[4][EXT][N];      // normalized ext embeddings, transposed [k][n]
__device__ float g_psc[2][N][NSLICES * KSEL];  // partial top-k scores
__device__ int   g_pix[2][N][NSLICES * KSEL];  // partial top-k indices

__device__ __forceinline__ float leaky(float x) { return fmaxf(x, 0.1f * x); }

// =====================================================================================
// Kernel P: feature projection + dist embedding + normalize + extended rows
// grid (N/32, 4 combos), 256 threads, dynamic smem 66816B
// =====================================================================================
__global__ __launch_bounds__(256) void kp(
    const float* __restrict__ pc1, const float* __restrict__ pc2,
    const float* __restrict__ feat1, const float* __restrict__ feat2,
    const float* __restrict__ t11w, const float* __restrict__ t11b,
    const float* __restrict__ t22w, const float* __restrict__ t22b,
    const float* __restrict__ dw, const float* __restrict__ db)
{
    extern __shared__ float sm[];
    float* s_tw   = sm;                    // [64][65]
    float* s_dw   = sm + 4160;             // [128][65]
    float* s_feat = sm + 4160 + 8320;      // [64][33]
    float* s_f    = sm + 4160 + 8320 + 2112; // [32][65]
    float* s_ss   = s_f + 2080;            // [32]

    const int combo = blockIdx.y;
    const float* feat = (combo == 0 || combo == 3) ? feat1 : feat2;
    const float* pc   = (combo == 0 || combo == 3) ? pc1   : pc2;
    const float* w    = (combo & 1) ? t22w : t11w;
    const float* b    = (combo & 1) ? t22b : t11b;
    const int side2   = combo & 1;

    const int tid = threadIdx.x;
    const int n0  = blockIdx.x * 32;

    for (int i = tid; i < 4096; i += 256) s_tw[(i >> 6) * 65 + (i & 63)] = w[i];
    for (int i = tid; i < 8192; i += 256) s_dw[(i >> 6) * 65 + (i & 63)] = dw[i];
    for (int i = tid; i < 64 * 32; i += 256) {
        int c = i >> 5, np = i & 31;
        s_feat[c * 33 + np] = feat[c * N + n0 + np];
    }
    if (tid < 32) s_ss[tid] = 0.f;
    __syncthreads();

    // f = t_w @ feat + t_b  (each thread: 8 (n,o) outputs)
    for (int it = 0; it < 8; ++it) {
        int i = tid + it * 256;
        int o = i & 63, n = i >> 6;
        float acc = __ldg(b + o);
        #pragma unroll
        for (int c = 0; c < 64; ++c)
            acc = fmaf(s_tw[o * 65 + c], s_feat[c * 33 + n], acc);
        s_f[n * 65 + o] = acc;
        g_f[combo][n0 + n][o] = acc;
    }
    __syncthreads();

    // g = dist_w @ f + dist_b, then normalize
    const int n = tid & 31, eg = tid >> 5;
    float gv[16];
    float ss = 0.f;
    #pragma unroll 2
    for (int t = 0; t < 16; ++t) {
        int e = eg * 16 + t;
        float acc = __ldg(db + e);
        #pragma unroll
        for (int c = 0; c < 64; ++c)
            acc = fmaf(s_dw[e * 65 + c], s_f[n * 65 + c], acc);
        gv[t] = acc;
        ss = fmaf(acc, acc, ss);
    }
    atomicAdd(&s_ss[n], ss);
    __syncthreads();
    const float scale = 1.f / (sqrtf(s_ss[n]) + 1e-8f);
    #pragma unroll
    for (int t = 0; t < 16; ++t) {
        int e = eg * 16 + t;
        g_gt[combo][e][n0 + n] = gv[t] * scale;
    }

    // extended rows: side1 -> [2x, -1]; side2 -> [x, |x|^2]
    if (tid < 32) {
        int nn = n0 + tid;
        float x0 = pc[0 * N + nn], x1 = pc[1 * N + nn], x2 = pc[2 * N + nn];
        if (side2) {
            g_gt[combo][128][nn] = x0;
            g_gt[combo][129][nn] = x1;
            g_gt[combo][130][nn] = x2;
            g_gt[combo][131][nn] = x0 * x0 + x1 * x1 + x2 * x2;
        } else {
            g_gt[combo][128][nn] = 2.f * x0;
            g_gt[combo][129][nn] = 2.f * x1;
            g_gt[combo][130][nn] = 2.f * x2;
            g_gt[combo][131][nn] = -1.f;
        }
    }
}

// =====================================================================================
// Kernel D: 132-dim score "GEMM" + per-row streaming top-16 (partial, per slice)
// grid (N/128 rowtiles, NSLICES, 2 dirs), 128 threads (1 row per thread)
// dynamic smem: s_a [EXT][128] (per-thread row spill) + s_b [TJ][EXT]
// =====================================================================================
__global__ __launch_bounds__(128, 3) void kd()
{
    extern __shared__ float sh[];
    float* s_a = sh;                 // [EXT][128]
    float* s_b = sh + EXT * DROWS;   // [TJ][EXT]

    const int tid  = threadIdx.x;
    const int dir  = blockIdx.z;
    const int row0 = blockIdx.x * DROWS;
    const int j0   = blockIdx.y * SLICE;

    const float* __restrict__ g1 = &g_gt[dir * 2][0][0];
    const float* __restrict__ g2 = &g_gt[dir * 2 + 1][0][0];

    // each thread stages its own extended row into its shared column (no sync needed)
    #pragma unroll 4
    for (int k = 0; k < EXT; ++k)
        s_a[k * DROWS + tid] = g1[k * N + row0 + tid];

    float ts[KSEL];
    int   ti[KSEL];
    #pragma unroll
    for (int q = 0; q < KSEL; ++q) { ts[q] = -FLT_MAX; ti[q] = 0; }

    for (int jt = 0; jt < SLICE; jt += TJ) {
        __syncthreads();
        for (int i = tid; i < TJ * EXT; i += 128) {
            int jj = i & (TJ - 1), k = i >> 3;
            s_b[jj * EXT + k] = g2[k * N + j0 + jt + jj];
        }
        __syncthreads();

        float acc[TJ];
        #pragma unroll
        for (int jj = 0; jj < TJ; ++jj) acc[jj] = 0.f;

        #pragma unroll 3
        for (int kc = 0; kc < EXT; kc += 4) {
            float a0 = s_a[(kc + 0) * DROWS + tid];
            float a1 = s_a[(kc + 1) * DROWS + tid];
            float a2 = s_a[(kc + 2) * DROWS + tid];
            float a3 = s_a[(kc + 3) * DROWS + tid];
            #pragma unroll
            for (int jj = 0; jj < TJ; ++jj) {
                float4 bv = *reinterpret_cast<const float4*>(&s_b[jj * EXT + kc]);
                acc[jj] = fmaf(a3, bv.w, fmaf(a2, bv.z, fmaf(a1, bv.y, fmaf(a0, bv.x, acc[jj]))));
            }
        }

        // batched top-16 insertion: bitmask of passers, drained warp-cooperatively
        unsigned m = 0;
        #pragma unroll
        for (int jj = 0; jj < TJ; ++jj)
            if (acc[jj] > ts[KSEL - 1]) m |= (1u << jj);

        while (__any_sync(0xffffffffu, m != 0)) {
            if (m) {
                int jj = __ffs(m) - 1;
                m &= m - 1;
                float cs = acc[jj];
                if (cs > ts[KSEL - 1]) {
                    int ci = j0 + jt + jj;
                    #pragma unroll
                    for (int q = 0; q < KSEL; ++q) {
                        if (cs > ts[q]) {
                            float tf = ts[q]; ts[q] = cs; cs = tf;
                            int   tx = ti[q]; ti[q] = ci; ci = tx;
                        }
                    }
                }
            }
        }
    }

    const int row = row0 + tid;
    const int sl  = blockIdx.y;
    #pragma unroll
    for (int q = 0; q < KSEL; ++q) {
        g_psc[dir][row][sl * KSEL + q] = ts[q];
        g_pix[dir][row][sl * KSEL + q] = ti[q];
    }
}

// =====================================================================================
// Kernel M: merge 256 partials -> exact top-16 (warp argmax on packed u64 keys),
// then gather + pos-conv + add + leaky + MLP + leaky + maxpool over K
// grid (N/8, 2 dirs), 256 threads (1 warp per row)
// =====================================================================================
__device__ __forceinline__ unsigned long long makeKey(float s, int j)
{
    unsigned u = __float_as_uint(s);
    u = (u & 0x80000000u) ? ~u : (u | 0x80000000u);   // monotone float->uint
    return ((unsigned long long)u << 32) | (unsigned)(~j); // tie -> smaller j wins
}

__global__ __launch_bounds__(256) void km(
    const float* __restrict__ pc1, const float* __restrict__ pc2,
    const float* __restrict__ posw, const float* __restrict__ posb,
    const float* __restrict__ mw, const float* __restrict__ mb,
    float* __restrict__ out)
{
    __shared__ float s_mw[64 * 65];
    __shared__ int   s_sel[8][KSEL];
    __shared__ float s_v[8][65];

    const int tid  = threadIdx.x;
    const int lane = tid & 31;
    const int rg   = tid >> 5;          // row-group (warp) 0..7
    const int dir  = blockIdx.y;
    const int row  = blockIdx.x * 8 + rg;

    const float* x1p = dir ? pc2 : pc1;
    const float* x2p = dir ? pc1 : pc2;
    const float* q1  = &g_f[dir * 2][0][0];
    const float* q2  = &g_f[dir * 2 + 1][0][0];

    for (int i = tid; i < 4096; i += 256)
        s_mw[(i >> 6) * 65 + (i & 63)] = mw[i];

    // --- build keys: lane owns elems lane + 32*t ---
    unsigned long long k[8];
    #pragma unroll
    for (int t = 0; t < 8; ++t) {
        int e = lane + 32 * t;
        k[t] = makeKey(g_psc[dir][row][e], g_pix[dir][row][e]);
    }

    // --- 16 rounds of warp argmax ---
    #pragma unroll 1
    for (int r = 0; r < KSEL; ++r) {
        unsigned long long m = k[0];
        #pragma unroll
        for (int t = 1; t < 8; ++t) m = (k[t] > m) ? k[t] : m;
        #pragma unroll
        for (int off = 16; off; off >>= 1) {
            unsigned long long o = __shfl_xor_sync(0xffffffffu, m, off);
            m = (o > m) ? o : m;
        }
        if (lane == 0) s_sel[rg][r] = (int)(~(unsigned)m);
        #pragma unroll
        for (int t = 0; t < 8; ++t)
            if (k[t] == m) k[t] = 0ULL;   // keys unique per row -> single owner
    }
    __syncthreads();   // covers s_mw and s_sel

    // --- gather + MLP; lane handles channels (lane, lane+32) ---
    const float x10 = x1p[row], x11 = x1p[N + row], x12 = x1p[2 * N + row];
    const float q1a = q1[row * 64 + lane];
    const float q1b = q1[row * 64 + lane + 32];
    const float pa0 = __ldg(posw + lane * 3 + 0), pa1 = __ldg(posw + lane * 3 + 1), pa2 = __ldg(posw + lane * 3 + 2);
    const float pb0 = __ldg(posw + (lane + 32) * 3 + 0), pb1 = __ldg(posw + (lane + 32) * 3 + 1), pb2 = __ldg(posw + (lane + 32) * 3 + 2);
    const float ba  = __ldg(posb + lane),      bb  = __ldg(posb + lane + 32);
    const float mba = __ldg(mb + lane),        mbb = __ldg(mb + lane + 32);

    float bestA = -FLT_MAX, bestB = -FLT_MAX;

    #pragma unroll 1
    for (int kk = 0; kk < KSEL; ++kk) {
        int j = s_sel[rg][kk];
        float d0 = x2p[j] - x10, d1 = x2p[N + j] - x11, d2 = x2p[2 * N + j] - x12;
        float posA = fmaf(pa2, d2, fmaf(pa1, d1, fmaf(pa0, d0, ba)));
        float posB = fmaf(pb2, d2, fmaf(pb1, d1, fmaf(pb0, d0, bb)));
        float va = leaky(q2[j * 64 + lane]      + q1a + posA);
        float vb = leaky(q2[j * 64 + lane + 32] + q1b + posB);
        s_v[rg][lane]      = va;
        s_v[rg][lane + 32] = vb;
        __syncwarp();
        float ha = mba, hb = mbb;
        #pragma unroll
        for (int c = 0; c < 64; ++c) {
            float vc = s_v[rg][c];
            ha = fmaf(s_mw[lane * 65 + c],        vc, ha);
            hb = fmaf(s_mw[(lane + 32) * 65 + c], vc, hb);
        }
        bestA = fmaxf(bestA, leaky(ha));
        bestB = fmaxf(bestB, leaky(hb));
        __syncwarp();
    }

    out[dir * (64 * N) + lane * N + row]        = bestA;
    out[dir * (64 * N) + (lane + 32) * N + row] = bestB;
}

// =====================================================================================
extern "C" void kernel_launch(void* const* d_in, const int* in_sizes, int n_in,
                              void* d_out, int out_size)
{
    const float* pc1   = (const float*)d_in[0];
    const float* pc2   = (const float*)d_in[1];
    const float* feat1 = (const float*)d_in[2];
    const float* feat2 = (const float*)d_in[3];
    const float* t11w  = (const float*)d_in[4];
    const float* t11b  = (const float*)d_in[5];
    const float* t22w  = (const float*)d_in[6];
    const float* t22b  = (const float*)d_in[7];
    const float* posw  = (const float*)d_in[8];
    const float* posb  = (const float*)d_in[9];
    const float* dw    = (const float*)d_in[10];
    const float* db    = (const float*)d_in[11];
    const float* mw    = (const float*)d_in[12];
    const float* mb    = (const float*)d_in[13];
    float* out = (float*)d_out;

    const int smP = 66816;
    const int smD = (EXT * DROWS + TJ * EXT) * (int)sizeof(float);  // 71808
    cudaFuncSetAttribute(kp, cudaFuncAttributeMaxDynamicSharedMemorySize, smP);
    cudaFuncSetAttribute(kd, cudaFuncAttributeMaxDynamicSharedMemorySize, smD);

    kp<<<dim3(N / 32, 4), 256, smP>>>(pc1, pc2, feat1, feat2,
                                      t11w, t11b, t22w, t22b, dw, db);
    kd<<<dim3(N / DROWS, NSLICES, 2), DROWS, smD>>>();
    km<<<dim3(N / 8, 2), 256>>>(pc1, pc2, posw, posb, mw, mb, out);
}